// round 14
// baseline (speedup 1.0000x reference)
#include <cuda_runtime.h>
#include <cuda_bf16.h>
#include <cuda_fp16.h>

#define NN   100000
#define EE   600000
#define HIDC 128
#define OUTC 40
#define GG   64
#define NB_SCAN 98           // ceil(100000/1024)
#define NTILE 1563           // ceil(100000/64) row tiles
#define GRID_G 152

// ---------------- persistent scratch ----------------------------------------
__device__ __half2 g_m2[NN*64];   // lin_r output (messages), fp16
__device__ float   g_hl[NN*HIDC]; // lin_l output, then normalized h2
__device__ int   g_off[NN+1];
__device__ int   g_cur[NN];
__device__ int   g_eid[EE];
__device__ int   g_bsum[NB_SCAN];
__device__ float g_cs1[3*HIDC];
__device__ float g_cs2[3*HIDC];
__device__ float g_pool[GG*HIDC];
__device__ int   g_gs[GG+1];

// ---------------- helpers -----------------------------------------------------
__device__ __forceinline__ unsigned s2u(const void* p) {
    unsigned a;
    asm("{ .reg .u64 t; cvta.to.shared.u64 t, %1; cvt.u32.u64 %0, t; }" : "=r"(a) : "l"(p));
    return a;
}
__device__ __forceinline__ void ldsm4(unsigned* r, unsigned addr) {
    asm volatile("ldmatrix.sync.aligned.m8n8.x4.shared.b16 {%0,%1,%2,%3}, [%4];"
        : "=r"(r[0]), "=r"(r[1]), "=r"(r[2]), "=r"(r[3]) : "r"(addr));
}
__device__ __forceinline__ void mma16816(float* d, const unsigned* a, const unsigned* b) {
    asm volatile("mma.sync.aligned.m16n8k16.row.col.f32.bf16.bf16.f32 "
        "{%0,%1,%2,%3}, {%4,%5,%6,%7}, {%8,%9}, {%0,%1,%2,%3};"
        : "+f"(d[0]), "+f"(d[1]), "+f"(d[2]), "+f"(d[3])
        : "r"(a[0]), "r"(a[1]), "r"(a[2]), "r"(a[3]), "r"(b[0]), "r"(b[1]));
}
__device__ __forceinline__ void cvt_hilo(float x, float y, unsigned& hi, unsigned& lo) {
    __nv_bfloat162 h = __floats2bfloat162_rn(x, y);
    float rx = x - __low2float(h);
    float ry = y - __high2float(h);
    __nv_bfloat162 l = __floats2bfloat162_rn(rx, ry);
    hi = *reinterpret_cast<unsigned*>(&h);
    lo = *reinterpret_cast<unsigned*>(&l);
}

// SMEM word layout (stride SA_W=68 words per row; 272B ≡ 16 mod 128 -> LDSM conflict-free)
#define SA_W 68
#define WB_WH   0                         // Wh [256][68]  (Wl hi rows 0-127, Wr hi rows 128-255)
#define WB_WO   (256*SA_W*4)              // Wo [128][68]  (Wl lo only)
#define WB_A    ((256+128)*SA_W*4)        // A: 2 bufs x (hi [64][68] ++ lo [64][68])
#define A_BUF_B (2*64*SA_W*4)             // 34816 bytes per buffer
#define A_LO_B  (64*SA_W*4)               // 17408
#define GEMM_SMEM_BYTES (WB_A + 2*A_BUF_B)   // 174080

// ---------------- CSR build / init -------------------------------------------
__global__ void k_zero() {
    int i = blockIdx.x*blockDim.x + threadIdx.x;
    if (i <= NN) g_off[i] = 0;
    if (i < 3*HIDC) { g_cs1[i] = 0.f; g_cs2[i] = 0.f; }
    if (i < GG*HIDC) g_pool[i] = 0.f;
}
__global__ void k_hist(const int* __restrict__ dst) {
    int e = blockIdx.x*blockDim.x + threadIdx.x;
    if (e < EE) atomicAdd(&g_off[dst[e]], 1);
}
__global__ void k_scan1() {
    __shared__ int s[1024];
    int t = threadIdx.x;
    int i = blockIdx.x*1024 + t;
    int v = (i < NN) ? g_off[i] : 0;
    s[t] = v;
    __syncthreads();
    for (int o = 1; o < 1024; o <<= 1) {
        int x = (t >= o) ? s[t-o] : 0;
        __syncthreads();
        s[t] += x;
        __syncthreads();
    }
    int incl = s[t];
    if (i < NN) g_off[i] = incl - v;
    if (t == 1023) g_bsum[blockIdx.x] = incl;
}
__global__ void k_scan2p() {
    __shared__ int s[128];
    int t = threadIdx.x;
    int v = (t < NB_SCAN) ? g_bsum[t] : 0;
    s[t] = v;
    __syncthreads();
    for (int o = 1; o < 128; o <<= 1) {
        int x = (t >= o) ? s[t-o] : 0;
        __syncthreads();
        s[t] += x;
        __syncthreads();
    }
    if (t < NB_SCAN) g_bsum[t] = s[t] - v;
}
__global__ void k_scan3() {
    int i = blockIdx.x*blockDim.x + threadIdx.x;
    if (i < NN) {
        int o = g_off[i] + g_bsum[i >> 10];
        g_off[i] = o;
        g_cur[i] = o;
    }
    if (i == 0) g_off[NN] = EE;
}
__global__ void k_fill(const int* __restrict__ src, const int* __restrict__ dst) {
    int e = blockIdx.x*blockDim.x + threadIdx.x;
    if (e < EE) {
        int d = dst[e];
        int p = atomicAdd(&g_cur[d], 1);
        g_eid[p] = src[e];
    }
}
__global__ void k_gstart(const int* __restrict__ batch) {
    int g = threadIdx.x;
    if (g > GG) return;
    if (g == GG) { g_gs[GG] = NN; return; }
    int lo = 0, hi = NN;
    while (lo < hi) { int mid = (lo + hi) >> 1; if (batch[mid] < g) lo = mid + 1; else hi = mid; }
    g_gs[g] = lo;
}

// ---------------- persistent tensor-core dual GEMM (512 thr, 16 warps) -------
// 64-row tile x 256 cols. 16 warps = 2(m32) x 8(n32); warp tile 32m x 32n.
// l-cols (0-127): AhBh+AlBh+AhBl; r-cols (128-255): AhBh+AlBh (messages fp16).
__global__ __launch_bounds__(512, 1) void k_gemm_tc(
    const float* __restrict__ Ain,       // null -> g_hl
    const float* __restrict__ Wl, const float* __restrict__ Wr,
    const float* __restrict__ bl, const float* __restrict__ br,
    const float* __restrict__ gamma, const float* __restrict__ beta,
    int bnslot)
{
    extern __shared__ __align__(16) unsigned sm[];
    unsigned* Wh = sm;                        // word pointers
    unsigned* Wo = sm + 256*SA_W;
    unsigned* Ab = sm + (256+128)*SA_W;
    const unsigned sb = s2u(sm);
    const float* A = Ain ? Ain : g_hl;
    int tid = threadIdx.x;

    // ---- load + split weights: Wl -> Wh(0-127)+Wo ; Wr -> Wh(128-255) hi only
    #pragma unroll
    for (int itr = 0; itr < 8; ++itr) {
        int idx = itr*512 + tid;              // 0..4095
        int n = idx >> 5, wq = idx & 31;
        float4 v = *(const float4*)(Wl + n*128 + wq*4);
        unsigned h0,l0,h1,l1;
        cvt_hilo(v.x, v.y, h0, l0);
        cvt_hilo(v.z, v.w, h1, l1);
        *(uint2*)(Wh + n*SA_W + 2*wq)       = make_uint2(h0, h1);
        *(uint2*)(Wo + n*SA_W + 2*wq)       = make_uint2(l0, l1);
        float4 w = *(const float4*)(Wr + n*128 + wq*4);
        cvt_hilo(w.x, w.y, h0, l0);
        cvt_hilo(w.z, w.w, h1, l1);
        *(uint2*)(Wh + (128+n)*SA_W + 2*wq) = make_uint2(h0, h1);
    }

    // ---- BN+ReLU coeffs for this thread's fixed 4 A-columns ----
    int kq = tid & 31, rbase = tid >> 5;      // A loader role: 16 rows apart
    float ca[4], cb[4];
    if (bnslot >= 0) {
        const float invn = 1.f / (float)NN;
        #pragma unroll
        for (int j = 0; j < 4; ++j) {
            int c = 4*kq + j;
            float mu  = g_cs1[bnslot*128 + c] * invn;
            float var = g_cs2[bnslot*128 + c] * invn - mu*mu;
            float aa  = gamma[c] * rsqrtf(var + 1e-5f);
            ca[j] = aa;
            cb[j] = beta[c] - mu*aa;
        }
    }

    int lane = tid & 31, g = lane >> 2, tg = lane & 3;
    int wid = tid >> 5, mw = wid & 1, nw = wid >> 1;   // 2 x 8 warp grid
    bool lside = (nw < 4);

    // per-warp bias registers (4 n8-tiles)
    float2 bias[4];
    #pragma unroll
    for (int nn = 0; nn < 4; ++nn) {
        int col = nw*32 + nn*8 + 2*tg;
        const float* bsrc = (col < 128) ? bl : br;
        bias[nn] = make_float2(bsrc[col & 127], bsrc[(col & 127) + 1]);
    }

    // ldmatrix per-lane byte offsets
    int quad = lane >> 3, lr = lane & 7;
    unsigned laneA = (unsigned)((lr + ((quad & 1) ? 8 : 0)) * (SA_W*4) + ((quad & 2) ? 16 : 0));
    unsigned laneB = (unsigned)((lr + ((quad & 2) ? 8 : 0)) * (SA_W*4) + ((quad & 1) ? 16 : 0));
    const unsigned bB0  = sb + WB_WH + (unsigned)(nw*32)*(SA_W*4) + laneB; // Wh rows nw*32..
    const unsigned boB0 = sb + WB_WO + (unsigned)(nw*32)*(SA_W*4) + laneB; // Wo (lside only)
    const unsigned aRow = (unsigned)(mw*32)*(SA_W*4) + laneA;

    // ---- first tile: prefetch + split into buf0 ----
    int t = blockIdx.x;
    int cur = 0;
    bool have = true;                          // GRID_G < NTILE
    float4 pf[4];
    {
        #pragma unroll
        for (int i2 = 0; i2 < 4; ++i2) {
            int row = t*64 + i2*16 + rbase;
            pf[i2] = (row < NN) ? *(const float4*)(A + (size_t)row*128 + kq*4)
                                : make_float4(0.f,0.f,0.f,0.f);
        }
        unsigned* Ah = Ab;                     // buf0 hi
        unsigned* Al = Ab + 64*SA_W;           // buf0 lo
        #pragma unroll
        for (int i2 = 0; i2 < 4; ++i2) {
            int rl = i2*16 + rbase;
            float4 v = pf[i2];
            if (bnslot >= 0) {
                v.x = fmaxf(ca[0]*v.x + cb[0], 0.f);
                v.y = fmaxf(ca[1]*v.y + cb[1], 0.f);
                v.z = fmaxf(ca[2]*v.z + cb[2], 0.f);
                v.w = fmaxf(ca[3]*v.w + cb[3], 0.f);
            }
            unsigned h0,l0,h1,l1;
            cvt_hilo(v.x, v.y, h0, l0);
            cvt_hilo(v.z, v.w, h1, l1);
            *(uint2*)(Ah + rl*SA_W + 2*kq) = make_uint2(h0, h1);
            *(uint2*)(Al + rl*SA_W + 2*kq) = make_uint2(l0, l1);
        }
    }

    while (have) {
        __syncthreads();                       // buf(cur) (and W on iter 1) visible
        int tn = t + GRID_G;
        bool nhave = (tn < NTILE);

        // prefetch next A tile (LDG overlaps MMAs below)
        if (nhave) {
            #pragma unroll
            for (int i2 = 0; i2 < 4; ++i2) {
                int row = tn*64 + i2*16 + rbase;
                pf[i2] = (row < NN) ? *(const float4*)(A + (size_t)row*128 + kq*4)
                                    : make_float4(0.f,0.f,0.f,0.f);
            }
        }

        // ---- MMA on buf(cur) ----
        const unsigned aHi0 = sb + WB_A + (unsigned)cur*A_BUF_B + aRow;
        const unsigned aLo0 = aHi0 + A_LO_B;
        int r0 = t*64;

        float acc[2][4][4];
        #pragma unroll
        for (int mm = 0; mm < 2; ++mm)
            #pragma unroll
            for (int nn = 0; nn < 4; ++nn) {
                acc[mm][nn][0] = bias[nn].x; acc[mm][nn][1] = bias[nn].y;
                acc[mm][nn][2] = bias[nn].x; acc[mm][nn][3] = bias[nn].y;
            }

        #pragma unroll
        for (int kc = 0; kc < 8; ++kc) {
            unsigned koff = (unsigned)kc*32;
            unsigned ah[2][4], al[2][4], bh[2][4], bo[2][4];
            #pragma unroll
            for (int mm = 0; mm < 2; ++mm) {
                ldsm4(ah[mm], aHi0 + (unsigned)mm*(16*SA_W*4) + koff);
                ldsm4(al[mm], aLo0 + (unsigned)mm*(16*SA_W*4) + koff);
            }
            #pragma unroll
            for (int p = 0; p < 2; ++p)
                ldsm4(bh[p], bB0 + (unsigned)p*(16*SA_W*4) + koff);
            if (lside) {
                #pragma unroll
                for (int p = 0; p < 2; ++p)
                    ldsm4(bo[p], boB0 + (unsigned)p*(16*SA_W*4) + koff);
            }
            #pragma unroll
            for (int mm = 0; mm < 2; ++mm)
                #pragma unroll
                for (int nn = 0; nn < 4; ++nn)
                    mma16816(acc[mm][nn], ah[mm], &bh[nn>>1][(nn&1)*2]);
            #pragma unroll
            for (int mm = 0; mm < 2; ++mm)
                #pragma unroll
                for (int nn = 0; nn < 4; ++nn)
                    mma16816(acc[mm][nn], al[mm], &bh[nn>>1][(nn&1)*2]);
            if (lside) {
                #pragma unroll
                for (int mm = 0; mm < 2; ++mm)
                    #pragma unroll
                    for (int nn = 0; nn < 4; ++nn)
                        mma16816(acc[mm][nn], ah[mm], &bo[nn>>1][(nn&1)*2]);
            }
        }

        // ---- epilogue: cols<128 -> g_hl fp32, cols>=128 -> g_m2 fp16 ----
        #pragma unroll
        for (int mm = 0; mm < 2; ++mm) {
            int row = r0 + mw*32 + mm*16 + g;
            #pragma unroll
            for (int nn = 0; nn < 4; ++nn) {
                int col = nw*32 + nn*8 + 2*tg;
                if (col < 128) {
                    if (row < NN)
                        *(float2*)(g_hl + (size_t)row*128 + col) =
                            make_float2(acc[mm][nn][0], acc[mm][nn][1]);
                    if (row + 8 < NN)
                        *(float2*)(g_hl + (size_t)(row+8)*128 + col) =
                            make_float2(acc[mm][nn][2], acc[mm][nn][3]);
                } else {
                    int mc = (col - 128) >> 1;
                    if (row < NN) {
                        __half2 hh = __floats2half2_rn(acc[mm][nn][0], acc[mm][nn][1]);
                        g_m2[(size_t)row*64 + mc] = hh;
                    }
                    if (row + 8 < NN) {
                        __half2 hh = __floats2half2_rn(acc[mm][nn][2], acc[mm][nn][3]);
                        g_m2[(size_t)(row+8)*64 + mc] = hh;
                    }
                }
            }
        }

        // ---- split prefetched tile into the other buffer ----
        if (nhave) {
            unsigned* nAh = Ab + (cur^1)*(2*64*SA_W);
            unsigned* nAl = nAh + 64*SA_W;
            #pragma unroll
            for (int i2 = 0; i2 < 4; ++i2) {
                int rl = i2*16 + rbase;
                float4 v = pf[i2];
                if (bnslot >= 0) {
                    v.x = fmaxf(ca[0]*v.x + cb[0], 0.f);
                    v.y = fmaxf(ca[1]*v.y + cb[1], 0.f);
                    v.z = fmaxf(ca[2]*v.z + cb[2], 0.f);
                    v.w = fmaxf(ca[3]*v.w + cb[3], 0.f);
                }
                unsigned h0,l0,h1,l1;
                cvt_hilo(v.x, v.y, h0, l0);
                cvt_hilo(v.z, v.w, h1, l1);
                *(uint2*)(nAh + rl*SA_W + 2*kq) = make_uint2(h0, h1);
                *(uint2*)(nAl + rl*SA_W + 2*kq) = make_uint2(l0, l1);
            }
        }
        t = tn; cur ^= 1; have = nhave;
    }
}

// ---------------- gather-mean + combine + L2 norm + BN stats -----------------
__global__ void k_agg(int slot) {
    __shared__ float s1[128], s2[128];
    int tid = threadIdx.x;
    if (tid < 128) { s1[tid] = 0.f; s2[tid] = 0.f; }
    __syncthreads();
    int lane = tid & 31;
    int wid  = blockIdx.x*8 + (tid >> 5);
    int nw   = gridDim.x*8;
    float c1x=0,c1y=0,c1z=0,c1w=0, c2x=0,c2y=0,c2z=0,c2w=0;
    for (int node = wid; node < NN; node += nw) {
        int e0 = g_off[node], e1 = g_off[node+1];
        float ax=0, ay=0, az=0, aw=0;
        for (int e = e0; e < e1; ++e) {
            int srow = g_eid[e];
            uint2 raw = *(const uint2*)(g_m2 + (size_t)srow*64 + lane*2);
            float2 f0 = __half22float2(*reinterpret_cast<__half2*>(&raw.x));
            float2 f1 = __half22float2(*reinterpret_cast<__half2*>(&raw.y));
            ax += f0.x; ay += f0.y; az += f1.x; aw += f1.y;
        }
        float inv = 1.f / fmaxf((float)(e1 - e0), 1.f);
        float4 h = *(const float4*)(g_hl + (size_t)node*128 + lane*4);
        h.x += ax*inv; h.y += ay*inv; h.z += az*inv; h.w += aw*inv;
        float ss = h.x*h.x + h.y*h.y + h.z*h.z + h.w*h.w;
        #pragma unroll
        for (int o = 16; o > 0; o >>= 1) ss += __shfl_xor_sync(0xffffffffu, ss, o);
        float sc = 1.f / fmaxf(sqrtf(ss), 1e-12f);
        h.x *= sc; h.y *= sc; h.z *= sc; h.w *= sc;
        *(float4*)(g_hl + (size_t)node*128 + lane*4) = h;
        c1x += h.x; c1y += h.y; c1z += h.z; c1w += h.w;
        c2x += h.x*h.x; c2y += h.y*h.y; c2z += h.z*h.z; c2w += h.w*h.w;
    }
    atomicAdd(&s1[lane*4+0], c1x); atomicAdd(&s1[lane*4+1], c1y);
    atomicAdd(&s1[lane*4+2], c1z); atomicAdd(&s1[lane*4+3], c1w);
    atomicAdd(&s2[lane*4+0], c2x); atomicAdd(&s2[lane*4+1], c2y);
    atomicAdd(&s2[lane*4+2], c2z); atomicAdd(&s2[lane*4+3], c2w);
    __syncthreads();
    if (tid < 128) {
        atomicAdd(&g_cs1[slot*128 + tid], s1[tid]);
        atomicAdd(&g_cs2[slot*128 + tid], s2[tid]);
    }
}

// ---------------- pooling (BN+ReLU of last layer fused, 8-way split) ---------
__global__ void k_pool(const float* __restrict__ gamma, const float* __restrict__ beta) {
    int g = blockIdx.x, p = blockIdx.y, t = threadIdx.x;
    const float invn = 1.f / (float)NN;
    float mu  = g_cs1[2*128 + t] * invn;
    float var = g_cs2[2*128 + t] * invn - mu*mu;
    float a   = gamma[t] * rsqrtf(var + 1e-5f);
    float b   = beta[t] - mu*a;
    int s0 = g_gs[g], e0 = g_gs[g+1], len = e0 - s0;
    int s = s0 + (len * p) / 8;
    int e = s0 + (len * (p+1)) / 8;
    float acc = 0.f;
    for (int node = s; node < e; ++node)
        acc += fmaxf(a * g_hl[(size_t)node*128 + t] + b, 0.f);
    atomicAdd(&g_pool[g*128 + t], acc);
}

__global__ void k_head(const float* __restrict__ W1, const float* __restrict__ b1,
                       const float* __restrict__ W2, const float* __restrict__ b2,
                       float* __restrict__ out)
{
    __shared__ float ps[128], us[128], ls[OUTC], st[2];
    int g = blockIdx.x, t = threadIdx.x;
    float cg = (float)(g_gs[g+1] - g_gs[g]);
    ps[t] = g_pool[g*128 + t];
    __syncthreads();
    float u = b1[t] * cg;
    #pragma unroll 8
    for (int k = 0; k < 128; ++k) u += ps[k] * W1[t*128 + k];
    us[t] = u;
    __syncthreads();
    if (t < OUTC) {
        float l = b2[t] * cg;
        #pragma unroll 8
        for (int k = 0; k < 128; ++k) l += us[k] * W2[t*128 + k];
        ls[t] = l;
    }
    __syncthreads();
    if (t == 0) {
        float mx = -1e30f;
        for (int j = 0; j < OUTC; ++j) mx = fmaxf(mx, ls[j]);
        float se = 0.f;
        for (int j = 0; j < OUTC; ++j) se += expf(ls[j] - mx);
        st[0] = mx; st[1] = logf(se);
    }
    __syncthreads();
    if (t < OUTC) out[g*OUTC + t] = ls[t] - st[0] - st[1];
}

// ---------------- launch ------------------------------------------------------
extern "C" void kernel_launch(void* const* d_in, const int* in_sizes, int n_in,
                              void* d_out, int out_size)
{
    const float* x     = (const float*)d_in[0];
    const int*   ei    = (const int*)  d_in[1];
    const int*   batch = (const int*)  d_in[2];
    const float* Wl    = (const float*)d_in[3];
    const float* bl    = (const float*)d_in[4];
    const float* Wr    = (const float*)d_in[5];
    const float* br    = (const float*)d_in[6];
    const float* gamma = (const float*)d_in[7];
    const float* beta  = (const float*)d_in[8];
    const float* W1    = (const float*)d_in[9];
    const float* b1    = (const float*)d_in[10];
    const float* W2    = (const float*)d_in[11];
    const float* b2    = (const float*)d_in[12];
    float* out = (float*)d_out;

    const int* src = ei;
    const int* dst = ei + EE;

    cudaFuncSetAttribute(k_gemm_tc, cudaFuncAttributeMaxDynamicSharedMemorySize,
                         GEMM_SMEM_BYTES);

    k_zero   <<<391, 256>>>();                         // 0
    k_hist   <<<2344, 256>>>(dst);                     // 1
    k_scan1  <<<NB_SCAN, 1024>>>();                    // 2
    k_gemm_tc<<<GRID_G, 512, GEMM_SMEM_BYTES>>>(       // 3  <- ncu target (layer 0)
        x, Wl, Wr, bl, br, gamma, beta, -1);
    k_scan2p <<<1, 128>>>();                           // 4
    k_scan3  <<<391, 256>>>();                         // 5
    k_fill   <<<2344, 256>>>(src, dst);                // 6
    k_gstart <<<1, GG+1>>>(batch);                     // 7

    k_agg<<<1480, 256>>>(0);                           // 8
    k_gemm_tc<<<GRID_G, 512, GEMM_SMEM_BYTES>>>(       // 9  (layer 1, BN slot 0)
        nullptr, Wl + 1*HIDC*HIDC, Wr + 1*HIDC*HIDC, bl + 1*HIDC, br + 1*HIDC,
        gamma + 0*HIDC, beta + 0*HIDC, 0);
    k_agg<<<1480, 256>>>(1);                           // 10
    k_gemm_tc<<<GRID_G, 512, GEMM_SMEM_BYTES>>>(       // 11 (layer 2, BN slot 1)
        nullptr, Wl + 2*HIDC*HIDC, Wr + 2*HIDC*HIDC, bl + 2*HIDC, br + 2*HIDC,
        gamma + 1*HIDC, beta + 1*HIDC, 1);
    k_agg<<<1480, 256>>>(2);                           // 12

    k_pool<<<dim3(GG, 8), 128>>>(gamma + 2*HIDC, beta + 2*HIDC);  // 13
    k_head<<<GG, 128>>>(W1, b1, W2, b2, out);                     // 14
}

// round 15
// speedup vs baseline: 1.2305x; 1.2305x over previous
#include <cuda_runtime.h>
#include <cuda_bf16.h>
#include <cuda_fp16.h>

#define NN   100000
#define EE   600000
#define HIDC 128
#define OUTC 40
#define GG   64
#define NB_SCAN 98           // ceil(100000/1024)
#define NTILE 1563           // ceil(100000/64) row tiles
#define GRID_G 152

// ---------------- persistent scratch ----------------------------------------
__device__ __half2 g_m2[NN*64];   // lin_r output (messages), fp16
__device__ float   g_hl[NN*HIDC]; // lin_l output, then normalized h2
__device__ int   g_off[NN+1];
__device__ int   g_cur[NN];
__device__ int   g_eid[EE];
__device__ int   g_bsum[NB_SCAN];
__device__ float g_cs1[3*HIDC];
__device__ float g_cs2[3*HIDC];
__device__ float g_pool[GG*HIDC];
__device__ int   g_gs[GG+1];

// ---------------- helpers -----------------------------------------------------
__device__ __forceinline__ unsigned s2u(const void* p) {
    unsigned a;
    asm("{ .reg .u64 t; cvta.to.shared.u64 t, %1; cvt.u32.u64 %0, t; }" : "=r"(a) : "l"(p));
    return a;
}
__device__ __forceinline__ void ldsm4(unsigned* r, unsigned addr) {
    asm volatile("ldmatrix.sync.aligned.m8n8.x4.shared.b16 {%0,%1,%2,%3}, [%4];"
        : "=r"(r[0]), "=r"(r[1]), "=r"(r[2]), "=r"(r[3]) : "r"(addr));
}
__device__ __forceinline__ void mma16816(float* d, const unsigned* a, const unsigned* b) {
    asm volatile("mma.sync.aligned.m16n8k16.row.col.f32.bf16.bf16.f32 "
        "{%0,%1,%2,%3}, {%4,%5,%6,%7}, {%8,%9}, {%0,%1,%2,%3};"
        : "+f"(d[0]), "+f"(d[1]), "+f"(d[2]), "+f"(d[3])
        : "r"(a[0]), "r"(a[1]), "r"(a[2]), "r"(a[3]), "r"(b[0]), "r"(b[1]));
}

// SMEM word layout (stride SA_W=68 words per row; 272B ≡ 16 mod 128 -> LDSM conflict-free)
#define SA_W 68
#define WB_WH   0                         // Wh [256][68] bf16 (Wl rows 0-127, Wr rows 128-255)
#define WB_A    (256*SA_W*4)              // A: 2 bufs x [64][68]
#define A_BUF_B (64*SA_W*4)               // 17408 bytes per buffer
#define GEMM_SMEM_BYTES (WB_A + 2*A_BUF_B)   // 104448

// ---------------- CSR build / init -------------------------------------------
__global__ void k_zero() {
    int i = blockIdx.x*blockDim.x + threadIdx.x;
    if (i <= NN) g_off[i] = 0;
    if (i < 3*HIDC) { g_cs1[i] = 0.f; g_cs2[i] = 0.f; }
    if (i < GG*HIDC) g_pool[i] = 0.f;
}
__global__ void k_hist(const int* __restrict__ dst) {
    int e = blockIdx.x*blockDim.x + threadIdx.x;
    if (e < EE) atomicAdd(&g_off[dst[e]], 1);
}
__global__ void k_scan1() {
    __shared__ int s[1024];
    int t = threadIdx.x;
    int i = blockIdx.x*1024 + t;
    int v = (i < NN) ? g_off[i] : 0;
    s[t] = v;
    __syncthreads();
    for (int o = 1; o < 1024; o <<= 1) {
        int x = (t >= o) ? s[t-o] : 0;
        __syncthreads();
        s[t] += x;
        __syncthreads();
    }
    int incl = s[t];
    if (i < NN) g_off[i] = incl - v;
    if (t == 1023) g_bsum[blockIdx.x] = incl;
}
__global__ void k_scan2p() {
    __shared__ int s[128];
    int t = threadIdx.x;
    int v = (t < NB_SCAN) ? g_bsum[t] : 0;
    s[t] = v;
    __syncthreads();
    for (int o = 1; o < 128; o <<= 1) {
        int x = (t >= o) ? s[t-o] : 0;
        __syncthreads();
        s[t] += x;
        __syncthreads();
    }
    if (t < NB_SCAN) g_bsum[t] = s[t] - v;
}
__global__ void k_scan3() {
    int i = blockIdx.x*blockDim.x + threadIdx.x;
    if (i < NN) {
        int o = g_off[i] + g_bsum[i >> 10];
        g_off[i] = o;
        g_cur[i] = o;
    }
    if (i == 0) g_off[NN] = EE;
}
__global__ void k_fill(const int* __restrict__ src, const int* __restrict__ dst) {
    int e = blockIdx.x*blockDim.x + threadIdx.x;
    if (e < EE) {
        int d = dst[e];
        int p = atomicAdd(&g_cur[d], 1);
        g_eid[p] = src[e];
    }
}
__global__ void k_gstart(const int* __restrict__ batch) {
    int g = threadIdx.x;
    if (g > GG) return;
    if (g == GG) { g_gs[GG] = NN; return; }
    int lo = 0, hi = NN;
    while (lo < hi) { int mid = (lo + hi) >> 1; if (batch[mid] < g) lo = mid + 1; else hi = mid; }
    g_gs[g] = lo;
}

// ---------------- persistent tensor-core dual GEMM (single-bf16, 1 term) -----
// 64-row tile x 256 cols. 16 warps = 2(m32) x 8(n32); warp tile 32m x 32n.
// Single bf16 precision both operands (L2/BN normalization damps the error;
// empirically validated by the r-side W-hi-only path since R13).
__global__ __launch_bounds__(512, 1) void k_gemm_tc(
    const float* __restrict__ Ain,       // null -> g_hl
    const float* __restrict__ Wl, const float* __restrict__ Wr,
    const float* __restrict__ bl, const float* __restrict__ br,
    const float* __restrict__ gamma, const float* __restrict__ beta,
    int bnslot)
{
    extern __shared__ __align__(16) unsigned sm[];
    unsigned* Wh = sm;                        // [256][68]
    unsigned* Ab = sm + 256*SA_W;             // 2 bufs x [64][68]
    const unsigned sb = s2u(sm);
    const float* A = Ain ? Ain : g_hl;
    int tid = threadIdx.x;

    // ---- load + convert both weight matrices to bf16 ----
    #pragma unroll
    for (int itr = 0; itr < 8; ++itr) {
        int idx = itr*512 + tid;              // 0..4095
        int n = idx >> 5, wq = idx & 31;
        float4 v = *(const float4*)(Wl + n*128 + wq*4);
        __nv_bfloat162 h0 = __floats2bfloat162_rn(v.x, v.y);
        __nv_bfloat162 h1 = __floats2bfloat162_rn(v.z, v.w);
        *(uint2*)(Wh + n*SA_W + 2*wq) =
            make_uint2(*reinterpret_cast<unsigned*>(&h0), *reinterpret_cast<unsigned*>(&h1));
        float4 w = *(const float4*)(Wr + n*128 + wq*4);
        h0 = __floats2bfloat162_rn(w.x, w.y);
        h1 = __floats2bfloat162_rn(w.z, w.w);
        *(uint2*)(Wh + (128+n)*SA_W + 2*wq) =
            make_uint2(*reinterpret_cast<unsigned*>(&h0), *reinterpret_cast<unsigned*>(&h1));
    }

    // ---- BN+ReLU coeffs for this thread's fixed 4 A-columns ----
    int kq = tid & 31, rbase = tid >> 5;      // A loader role: rows 16 apart
    float ca[4], cb[4];
    if (bnslot >= 0) {
        const float invn = 1.f / (float)NN;
        #pragma unroll
        for (int j = 0; j < 4; ++j) {
            int c = 4*kq + j;
            float mu  = g_cs1[bnslot*128 + c] * invn;
            float var = g_cs2[bnslot*128 + c] * invn - mu*mu;
            float aa  = gamma[c] * rsqrtf(var + 1e-5f);
            ca[j] = aa;
            cb[j] = beta[c] - mu*aa;
        }
    }

    int lane = tid & 31, g = lane >> 2, tg = lane & 3;
    int wid = tid >> 5, mw = wid & 1, nw = wid >> 1;   // 2 x 8 warp grid

    // per-warp bias registers (4 n8-tiles)
    float2 bias[4];
    #pragma unroll
    for (int nn = 0; nn < 4; ++nn) {
        int col = nw*32 + nn*8 + 2*tg;
        const float* bsrc = (col < 128) ? bl : br;
        bias[nn] = make_float2(bsrc[col & 127], bsrc[(col & 127) + 1]);
    }

    // ldmatrix per-lane byte offsets
    int quad = lane >> 3, lr = lane & 7;
    unsigned laneA = (unsigned)((lr + ((quad & 1) ? 8 : 0)) * (SA_W*4) + ((quad & 2) ? 16 : 0));
    unsigned laneB = (unsigned)((lr + ((quad & 2) ? 8 : 0)) * (SA_W*4) + ((quad & 1) ? 16 : 0));
    const unsigned bB0  = sb + WB_WH + (unsigned)(nw*32)*(SA_W*4) + laneB; // Wh rows nw*32..
    const unsigned aRow = (unsigned)(mw*32)*(SA_W*4) + laneA;

    // ---- first tile: prefetch + convert into buf0 ----
    int t = blockIdx.x;
    int cur = 0;
    bool have = true;                          // GRID_G < NTILE
    float4 pf[4];
    {
        #pragma unroll
        for (int i2 = 0; i2 < 4; ++i2) {
            int row = t*64 + i2*16 + rbase;
            pf[i2] = (row < NN) ? *(const float4*)(A + (size_t)row*128 + kq*4)
                                : make_float4(0.f,0.f,0.f,0.f);
        }
        unsigned* Ah = Ab;                     // buf0
        #pragma unroll
        for (int i2 = 0; i2 < 4; ++i2) {
            int rl = i2*16 + rbase;
            float4 v = pf[i2];
            if (bnslot >= 0) {
                v.x = fmaxf(ca[0]*v.x + cb[0], 0.f);
                v.y = fmaxf(ca[1]*v.y + cb[1], 0.f);
                v.z = fmaxf(ca[2]*v.z + cb[2], 0.f);
                v.w = fmaxf(ca[3]*v.w + cb[3], 0.f);
            }
            __nv_bfloat162 h0 = __floats2bfloat162_rn(v.x, v.y);
            __nv_bfloat162 h1 = __floats2bfloat162_rn(v.z, v.w);
            *(uint2*)(Ah + rl*SA_W + 2*kq) =
                make_uint2(*reinterpret_cast<unsigned*>(&h0), *reinterpret_cast<unsigned*>(&h1));
        }
    }

    while (have) {
        __syncthreads();                       // buf(cur) (and W on iter 1) visible
        int tn = t + GRID_G;
        bool nhave = (tn < NTILE);

        // prefetch next A tile (LDG overlaps MMAs below)
        if (nhave) {
            #pragma unroll
            for (int i2 = 0; i2 < 4; ++i2) {
                int row = tn*64 + i2*16 + rbase;
                pf[i2] = (row < NN) ? *(const float4*)(A + (size_t)row*128 + kq*4)
                                    : make_float4(0.f,0.f,0.f,0.f);
            }
        }

        // ---- MMA on buf(cur) ----
        const unsigned aHi0 = sb + WB_A + (unsigned)cur*A_BUF_B + aRow;
        int r0 = t*64;

        float acc[2][4][4];
        #pragma unroll
        for (int mm = 0; mm < 2; ++mm)
            #pragma unroll
            for (int nn = 0; nn < 4; ++nn) {
                acc[mm][nn][0] = bias[nn].x; acc[mm][nn][1] = bias[nn].y;
                acc[mm][nn][2] = bias[nn].x; acc[mm][nn][3] = bias[nn].y;
            }

        #pragma unroll
        for (int kc = 0; kc < 8; ++kc) {
            unsigned koff = (unsigned)kc*32;
            unsigned ah[2][4], bh[2][4];
            #pragma unroll
            for (int mm = 0; mm < 2; ++mm)
                ldsm4(ah[mm], aHi0 + (unsigned)mm*(16*SA_W*4) + koff);
            #pragma unroll
            for (int p = 0; p < 2; ++p)
                ldsm4(bh[p], bB0 + (unsigned)p*(16*SA_W*4) + koff);
            #pragma unroll
            for (int mm = 0; mm < 2; ++mm)
                #pragma unroll
                for (int nn = 0; nn < 4; ++nn)
                    mma16816(acc[mm][nn], ah[mm], &bh[nn>>1][(nn&1)*2]);
        }

        // ---- epilogue: cols<128 -> g_hl fp32, cols>=128 -> g_m2 fp16 ----
        #pragma unroll
        for (int mm = 0; mm < 2; ++mm) {
            int row = r0 + mw*32 + mm*16 + g;
            #pragma unroll
            for (int nn = 0; nn < 4; ++nn) {
                int col = nw*32 + nn*8 + 2*tg;
                if (col < 128) {
                    if (row < NN)
                        *(float2*)(g_hl + (size_t)row*128 + col) =
                            make_float2(acc[mm][nn][0], acc[mm][nn][1]);
                    if (row + 8 < NN)
                        *(float2*)(g_hl + (size_t)(row+8)*128 + col) =
                            make_float2(acc[mm][nn][2], acc[mm][nn][3]);
                } else {
                    int mc = (col - 128) >> 1;
                    if (row < NN) {
                        __half2 hh = __floats2half2_rn(acc[mm][nn][0], acc[mm][nn][1]);
                        g_m2[(size_t)row*64 + mc] = hh;
                    }
                    if (row + 8 < NN) {
                        __half2 hh = __floats2half2_rn(acc[mm][nn][2], acc[mm][nn][3]);
                        g_m2[(size_t)(row+8)*64 + mc] = hh;
                    }
                }
            }
        }

        // ---- convert prefetched tile into the other buffer ----
        if (nhave) {
            unsigned* nAh = Ab + (cur^1)*(64*SA_W);
            #pragma unroll
            for (int i2 = 0; i2 < 4; ++i2) {
                int rl = i2*16 + rbase;
                float4 v = pf[i2];
                if (bnslot >= 0) {
                    v.x = fmaxf(ca[0]*v.x + cb[0], 0.f);
                    v.y = fmaxf(ca[1]*v.y + cb[1], 0.f);
                    v.z = fmaxf(ca[2]*v.z + cb[2], 0.f);
                    v.w = fmaxf(ca[3]*v.w + cb[3], 0.f);
                }
                __nv_bfloat162 h0 = __floats2bfloat162_rn(v.x, v.y);
                __nv_bfloat162 h1 = __floats2bfloat162_rn(v.z, v.w);
                *(uint2*)(nAh + rl*SA_W + 2*kq) =
                    make_uint2(*reinterpret_cast<unsigned*>(&h0), *reinterpret_cast<unsigned*>(&h1));
            }
        }
        t = tn; cur ^= 1; have = nhave;
    }
}

// ---------------- gather-mean + combine + L2 norm + BN stats -----------------
__global__ void k_agg(int slot) {
    __shared__ float s1[128], s2[128];
    int tid = threadIdx.x;
    if (tid < 128) { s1[tid] = 0.f; s2[tid] = 0.f; }
    __syncthreads();
    int lane = tid & 31;
    int wid  = blockIdx.x*8 + (tid >> 5);
    int nw   = gridDim.x*8;
    float c1x=0,c1y=0,c1z=0,c1w=0, c2x=0,c2y=0,c2z=0,c2w=0;
    for (int node = wid; node < NN; node += nw) {
        int e0 = g_off[node], e1 = g_off[node+1];
        float ax=0, ay=0, az=0, aw=0;
        for (int e = e0; e < e1; ++e) {
            int srow = g_eid[e];
            uint2 raw = *(const uint2*)(g_m2 + (size_t)srow*64 + lane*2);
            float2 f0 = __half22float2(*reinterpret_cast<__half2*>(&raw.x));
            float2 f1 = __half22float2(*reinterpret_cast<__half2*>(&raw.y));
            ax += f0.x; ay += f0.y; az += f1.x; aw += f1.y;
        }
        float inv = 1.f / fmaxf((float)(e1 - e0), 1.f);
        float4 h = *(const float4*)(g_hl + (size_t)node*128 + lane*4);
        h.x += ax*inv; h.y += ay*inv; h.z += az*inv; h.w += aw*inv;
        float ss = h.x*h.x + h.y*h.y + h.z*h.z + h.w*h.w;
        #pragma unroll
        for (int o = 16; o > 0; o >>= 1) ss += __shfl_xor_sync(0xffffffffu, ss, o);
        float sc = 1.f / fmaxf(sqrtf(ss), 1e-12f);
        h.x *= sc; h.y *= sc; h.z *= sc; h.w *= sc;
        *(float4*)(g_hl + (size_t)node*128 + lane*4) = h;
        c1x += h.x; c1y += h.y; c1z += h.z; c1w += h.w;
        c2x += h.x*h.x; c2y += h.y*h.y; c2z += h.z*h.z; c2w += h.w*h.w;
    }
    atomicAdd(&s1[lane*4+0], c1x); atomicAdd(&s1[lane*4+1], c1y);
    atomicAdd(&s1[lane*4+2], c1z); atomicAdd(&s1[lane*4+3], c1w);
    atomicAdd(&s2[lane*4+0], c2x); atomicAdd(&s2[lane*4+1], c2y);
    atomicAdd(&s2[lane*4+2], c2z); atomicAdd(&s2[lane*4+3], c2w);
    __syncthreads();
    if (tid < 128) {
        atomicAdd(&g_cs1[slot*128 + tid], s1[tid]);
        atomicAdd(&g_cs2[slot*128 + tid], s2[tid]);
    }
}

// ---------------- pooling (BN+ReLU of last layer fused, 8-way split) ---------
__global__ void k_pool(const float* __restrict__ gamma, const float* __restrict__ beta) {
    int g = blockIdx.x, p = blockIdx.y, t = threadIdx.x;
    const float invn = 1.f / (float)NN;
    float mu  = g_cs1[2*128 + t] * invn;
    float var = g_cs2[2*128 + t] * invn - mu*mu;
    float a   = gamma[t] * rsqrtf(var + 1e-5f);
    float b   = beta[t] - mu*a;
    int s0 = g_gs[g], e0 = g_gs[g+1], len = e0 - s0;
    int s = s0 + (len * p) / 8;
    int e = s0 + (len * (p+1)) / 8;
    float acc = 0.f;
    for (int node = s; node < e; ++node)
        acc += fmaxf(a * g_hl[(size_t)node*128 + t] + b, 0.f);
    atomicAdd(&g_pool[g*128 + t], acc);
}

__global__ void k_head(const float* __restrict__ W1, const float* __restrict__ b1,
                       const float* __restrict__ W2, const float* __restrict__ b2,
                       float* __restrict__ out)
{
    __shared__ float ps[128], us[128], ls[OUTC], st[2];
    int g = blockIdx.x, t = threadIdx.x;
    float cg = (float)(g_gs[g+1] - g_gs[g]);
    ps[t] = g_pool[g*128 + t];
    __syncthreads();
    float u = b1[t] * cg;
    #pragma unroll 8
    for (int k = 0; k < 128; ++k) u += ps[k] * W1[t*128 + k];
    us[t] = u;
    __syncthreads();
    if (t < OUTC) {
        float l = b2[t] * cg;
        #pragma unroll 8
        for (int k = 0; k < 128; ++k) l += us[k] * W2[t*128 + k];
        ls[t] = l;
    }
    __syncthreads();
    if (t == 0) {
        float mx = -1e30f;
        for (int j = 0; j < OUTC; ++j) mx = fmaxf(mx, ls[j]);
        float se = 0.f;
        for (int j = 0; j < OUTC; ++j) se += expf(ls[j] - mx);
        st[0] = mx; st[1] = logf(se);
    }
    __syncthreads();
    if (t < OUTC) out[g*OUTC + t] = ls[t] - st[0] - st[1];
}

// ---------------- launch ------------------------------------------------------
extern "C" void kernel_launch(void* const* d_in, const int* in_sizes, int n_in,
                              void* d_out, int out_size)
{
    const float* x     = (const float*)d_in[0];
    const int*   ei    = (const int*)  d_in[1];
    const int*   batch = (const int*)  d_in[2];
    const float* Wl    = (const float*)d_in[3];
    const float* bl    = (const float*)d_in[4];
    const float* Wr    = (const float*)d_in[5];
    const float* br    = (const float*)d_in[6];
    const float* gamma = (const float*)d_in[7];
    const float* beta  = (const float*)d_in[8];
    const float* W1    = (const float*)d_in[9];
    const float* b1    = (const float*)d_in[10];
    const float* W2    = (const float*)d_in[11];
    const float* b2    = (const float*)d_in[12];
    float* out = (float*)d_out;

    const int* src = ei;
    const int* dst = ei + EE;

    cudaFuncSetAttribute(k_gemm_tc, cudaFuncAttributeMaxDynamicSharedMemorySize,
                         GEMM_SMEM_BYTES);

    k_zero   <<<391, 256>>>();                         // 0
    k_hist   <<<2344, 256>>>(dst);                     // 1
    k_scan1  <<<NB_SCAN, 1024>>>();                    // 2
    k_gemm_tc<<<GRID_G, 512, GEMM_SMEM_BYTES>>>(       // 3  <- ncu target (layer 0)
        x, Wl, Wr, bl, br, gamma, beta, -1);
    k_scan2p <<<1, 128>>>();                           // 4
    k_scan3  <<<391, 256>>>();                         // 5
    k_fill   <<<2344, 256>>>(src, dst);                // 6
    k_gstart <<<1, GG+1>>>(batch);                     // 7

    k_agg<<<1480, 256>>>(0);                           // 8
    k_gemm_tc<<<GRID_G, 512, GEMM_SMEM_BYTES>>>(       // 9  (layer 1, BN slot 0)
        nullptr, Wl + 1*HIDC*HIDC, Wr + 1*HIDC*HIDC, bl + 1*HIDC, br + 1*HIDC,
        gamma + 0*HIDC, beta + 0*HIDC, 0);
    k_agg<<<1480, 256>>>(1);                           // 10
    k_gemm_tc<<<GRID_G, 512, GEMM_SMEM_BYTES>>>(       // 11 (layer 2, BN slot 1)
        nullptr, Wl + 2*HIDC*HIDC, Wr + 2*HIDC*HIDC, bl + 2*HIDC, br + 2*HIDC,
        gamma + 1*HIDC, beta + 1*HIDC, 1);
    k_agg<<<1480, 256>>>(2);                           // 12

    k_pool<<<dim3(GG, 8), 128>>>(gamma + 2*HIDC, beta + 2*HIDC);  // 13
    k_head<<<GG, 128>>>(W1, b1, W2, b2, out);                     // 14
}